// round 10
// baseline (speedup 1.0000x reference)
#include <cuda_runtime.h>
#include <cuda_bf16.h>
#include <math.h>

#define HWSZ 12544      // 112*112
#define IMGW 112
#define NB   16
#define EPSV 1e-5f

// ---- scratch (tiny) ----
__device__ float g_pooled[NB * 64];
__device__ float g_k1[NB * 64 * 64];   // [b][o][i], BN1 scale folded
__device__ float g_sum1[NB * 64];      // post-act x1 channel sums
__device__ float g_sum2[NB * 64];      // post-act x2 channel sums
__device__ float g_gates[NB * 128];

__device__ __forceinline__ float sigmoidf_(float x) { return 1.f / (1.f + expf(-x)); }

__device__ __forceinline__ unsigned smem_u32(const void* p) {
    unsigned r;
    asm("{ .reg .u64 t; cvta.to.shared.u64 t, %1; cvt.u32.u64 %0, t; }" : "=r"(r) : "l"(p));
    return r;
}
// pack two floats -> bf16x2 word: low half = lo, high half = hi
__device__ __forceinline__ unsigned pack_bf16x2(float lo, float hi) {
    unsigned r;
    asm("cvt.rn.bf16x2.f32 %0, %1, %2;" : "=r"(r) : "f"(hi), "f"(lo));
    return r;
}
#define LDSM_X4(r0, r1, r2, r3, addr) \
    asm volatile("ldmatrix.sync.aligned.m8n8.x4.shared.b16 {%0,%1,%2,%3}, [%4];" \
                 : "=r"(r0), "=r"(r1), "=r"(r2), "=r"(r3) : "r"(addr))
#define LDSM_X2_T(r0, r1, addr) \
    asm volatile("ldmatrix.sync.aligned.m8n8.x2.trans.shared.b16 {%0,%1}, [%2];" \
                 : "=r"(r0), "=r"(r1) : "r"(addr))
#define MMA_BF16(c, a, b) \
    asm volatile("mma.sync.aligned.m16n8k16.row.col.f32.bf16.bf16.f32 " \
                 "{%0,%1,%2,%3}, {%4,%5,%6,%7}, {%8,%9}, {%0,%1,%2,%3};" \
                 : "+f"((c)[0]), "+f"((c)[1]), "+f"((c)[2]), "+f"((c)[3]) \
                 : "r"((a)[0]), "r"((a)[1]), "r"((a)[2]), "r"((a)[3]), \
                   "r"((b)[0]), "r"((b)[1]))

// ---- mean over HW per (b,c) + zero sums: grid 1024 x 256 ----
__global__ __launch_bounds__(256) void pool1_kernel(const float* __restrict__ x) {
    int bc = blockIdx.x;
    if (threadIdx.x == 0) { g_sum1[bc] = 0.f; g_sum2[bc] = 0.f; }
    const float4* p = (const float4*)(x + (size_t)bc * HWSZ);
    float s = 0.f;
    for (int i = threadIdx.x; i < HWSZ / 4; i += 256) {
        float4 v = p[i];
        s += v.x + v.y + v.z + v.w;
    }
    for (int o = 16; o; o >>= 1) s += __shfl_xor_sync(0xffffffffu, s, o);
    __shared__ float red[8];
    if ((threadIdx.x & 31) == 0) red[threadIdx.x >> 5] = s;
    __syncthreads();
    if (threadIdx.x < 8) {
        s = red[threadIdx.x];
        for (int o = 4; o; o >>= 1) s += __shfl_xor_sync(0xffu, s, o);
        if (threadIdx.x == 0) g_pooled[bc] = s * (1.f / (float)HWSZ);
    }
}

// ---- r1 + mixed 1x1 kernel (BN1 scale folded), [o][i] layout: grid NB x 256 ----
__global__ __launch_bounds__(256) void build_k1_kernel(
    const float* __restrict__ rw1, const float* __restrict__ rb1,
    const float* __restrict__ w1,
    const float* __restrict__ g1, const float* __restrict__ v1) {
    int b = blockIdx.x;
    __shared__ float r1s[4];
    if (threadIdx.x < 4) {
        int e = threadIdx.x;
        float a = rb1[e];
        for (int i = 0; i < 64; i++) a += g_pooled[b * 64 + i] * rw1[e * 64 + i];
        r1s[e] = sigmoidf_(a);
    }
    __syncthreads();
    for (int idx = threadIdx.x; idx < 4096; idx += 256) {
        int o = idx >> 6;
        float a = 0.f;
#pragma unroll
        for (int e = 0; e < 4; e++) a += r1s[e] * w1[e * 4096 + idx];
        float sc = g1[o] * rsqrtf(v1[o] + EPSV);
        g_k1[b * 4096 + idx] = a * sc;    // layout [o][i]
    }
}

// ---- dynamic 1x1 conv via bf16-split tensor cores (round-8 proven) ----
#define KROW 72     // A row pad (bf16): 144B -> 16B bank phase
#define XROW 264    // B row pad (bf16): 528B -> 16B bank phase
__global__ __launch_bounds__(256, 2) void conv1_mma_kernel(
    const float* __restrict__ x,
    const float* __restrict__ g1, const float* __restrict__ b1,
    const float* __restrict__ m1, const float* __restrict__ v1,
    float* __restrict__ out) {
    extern __shared__ __nv_bfloat16 cs[];
    __nv_bfloat16* kh = cs;                    // [64][KROW]
    __nv_bfloat16* kl = kh + 64 * KROW;
    __nv_bfloat16* xh = kl + 64 * KROW;        // [64][XROW]
    __nv_bfloat16* xl = xh + 64 * XROW;
    const unsigned FULL = 0xffffffffu;

    int b = blockIdx.y;
    int p0 = blockIdx.x * 256;
    int tid = threadIdx.x;

#pragma unroll
    for (int t = 0; t < 16; t++) {
        int idx = tid + 256 * t;               // f4 index
        int row = idx >> 6, col = (idx & 63) << 2;
        float4 v = *(const float4*)&x[((size_t)(b * 64 + row)) * HWSZ + p0 + col];
        float h0 = __bfloat162float(__float2bfloat16(v.x));
        float h1 = __bfloat162float(__float2bfloat16(v.y));
        float h2 = __bfloat162float(__float2bfloat16(v.z));
        float h3 = __bfloat162float(__float2bfloat16(v.w));
        uint2 hw = make_uint2(pack_bf16x2(v.x, v.y), pack_bf16x2(v.z, v.w));
        uint2 lw = make_uint2(pack_bf16x2(v.x - h0, v.y - h1),
                              pack_bf16x2(v.z - h2, v.w - h3));
        *(uint2*)&xh[row * XROW + col] = hw;
        *(uint2*)&xl[row * XROW + col] = lw;
    }
#pragma unroll
    for (int t = 0; t < 8; t++) {
        int pidx = tid + 256 * t;              // pair index 0..2047
        int o = pidx >> 5, i2 = (pidx & 31) << 1;
        float a0 = g_k1[b * 4096 + o * 64 + i2];
        float a1 = g_k1[b * 4096 + o * 64 + i2 + 1];
        float h0 = __bfloat162float(__float2bfloat16(a0));
        float h1 = __bfloat162float(__float2bfloat16(a1));
        *(unsigned*)&kh[o * KROW + i2] = pack_bf16x2(a0, a1);
        *(unsigned*)&kl[o * KROW + i2] = pack_bf16x2(a0 - h0, a1 - h1);
    }
    __syncthreads();

    int warp = tid >> 5, lane = tid & 31;
    int mw = warp & 3, nw = warp >> 2;

    float C[16][4];
#pragma unroll
    for (int j = 0; j < 16; j++)
#pragma unroll
        for (int q = 0; q < 4; q++) C[j][q] = 0.f;

    int arow = mw * 16 + (lane & 15);
    int acol = (lane & 16) ? 8 : 0;
    unsigned a_h = smem_u32(kh) + (arow * KROW + acol) * 2;
    unsigned a_l = smem_u32(kl) + (arow * KROW + acol) * 2;
    unsigned b_h0 = smem_u32(xh) + ((lane & 15) * XROW + nw * 128) * 2;
    unsigned b_l0 = smem_u32(xl) + ((lane & 15) * XROW + nw * 128) * 2;

#pragma unroll
    for (int kt = 0; kt < 4; kt++) {
        unsigned Ah[4], Al[4];
        LDSM_X4(Ah[0], Ah[1], Ah[2], Ah[3], a_h + kt * 16 * 2);
        LDSM_X4(Al[0], Al[1], Al[2], Al[3], a_l + kt * 16 * 2);
        unsigned bh = b_h0 + kt * 16 * XROW * 2;
        unsigned bl = b_l0 + kt * 16 * XROW * 2;
#pragma unroll
        for (int j = 0; j < 16; j++) {
            unsigned Bh[2], Bl[2];
            LDSM_X2_T(Bh[0], Bh[1], bh + j * 16);
            LDSM_X2_T(Bl[0], Bl[1], bl + j * 16);
            MMA_BF16(C[j], Ah, Bh);
            MMA_BF16(C[j], Ah, Bl);
            MMA_BF16(C[j], Al, Bh);
        }
    }

    int r0 = mw * 16 + (lane >> 2);
    int r1 = r0 + 8;
    float sc0 = g1[r0] * rsqrtf(v1[r0] + EPSV);
    float sh0 = b1[r0] - m1[r0] * sc0;
    float sc1 = g1[r1] * rsqrtf(v1[r1] + EPSV);
    float sh1 = b1[r1] - m1[r1] * sc1;
    float* op0 = out + ((size_t)(b * 128 + r0)) * HWSZ + p0 + nw * 128 + (lane & 3) * 2;
    float* op1 = out + ((size_t)(b * 128 + r1)) * HWSZ + p0 + nw * 128 + (lane & 3) * 2;
    float s0 = 0.f, s1 = 0.f;
#pragma unroll
    for (int j = 0; j < 16; j++) {
        float c0 = fmaxf(C[j][0] + sh0, 0.f), c1 = fmaxf(C[j][1] + sh0, 0.f);
        float c2 = fmaxf(C[j][2] + sh1, 0.f), c3 = fmaxf(C[j][3] + sh1, 0.f);
        *(float2*)&op0[j * 8] = make_float2(c0, c1);
        *(float2*)&op1[j * 8] = make_float2(c2, c3);
        s0 += c0 + c1; s1 += c2 + c3;
    }
    s0 += __shfl_xor_sync(FULL, s0, 1); s0 += __shfl_xor_sync(FULL, s0, 2);
    s1 += __shfl_xor_sync(FULL, s1, 1); s1 += __shfl_xor_sync(FULL, s1, 2);
    if ((lane & 3) == 0) {
        atomicAdd(&g_sum1[b * 64 + r0], s0);
        atomicAdd(&g_sum1[b * 64 + r1], s1);
    }
}

// ---- dynamic 3x3 depthwise: pipelined register-rolling stencil ----
// one warp = one (channel, 16-row strip); block 128 (4 warps), grid 1792
__global__ __launch_bounds__(128) void dw_kernel(
    const float* __restrict__ rw2, const float* __restrict__ rb2,
    const float* __restrict__ w2,
    const float* __restrict__ g2, const float* __restrict__ b2,
    const float* __restrict__ m2, const float* __restrict__ v2,
    float* __restrict__ out) {
    const unsigned FULL = 0xffffffffu;
    int lane = threadIdx.x & 31;
    int gw = blockIdx.x * 4 + (threadIdx.x >> 5);   // 0..7167
    int bc = gw / 7, s7 = gw % 7;
    int b = bc >> 6, c = bc & 63;
    const float* in = out + ((size_t)(b * 128 + c)) * HWSZ;       // x1 channel
    float* op = out + ((size_t)(b * 128 + 64 + c)) * HWSZ;        // x2 channel

    // per-warp k2 mix
    float r2 = 0.f;
    if (lane < 4) {
        float a = rb2[lane];
        const float* rw = rw2 + lane * 64;
        const float* su = g_sum1 + b * 64;
#pragma unroll 8
        for (int cc = 0; cc < 64; cc++) a += su[cc] * (1.f / (float)HWSZ) * rw[cc];
        r2 = sigmoidf_(a);
    }
    float sc = g2[c] * rsqrtf(v2[c] + EPSV);
    float kv = 0.f;
    {
        float e0 = __shfl_sync(FULL, r2, 0), e1 = __shfl_sync(FULL, r2, 1);
        float e2 = __shfl_sync(FULL, r2, 2), e3 = __shfl_sync(FULL, r2, 3);
        if (lane < 9) {
            const float* wp = w2 + c * 9 + lane;
            kv = (e0 * wp[0] + e1 * wp[576] + e2 * wp[1152] + e3 * wp[1728]) * sc;
        }
    }
    float k0 = __shfl_sync(FULL, kv, 0), k1 = __shfl_sync(FULL, kv, 1), k2 = __shfl_sync(FULL, kv, 2);
    float k3 = __shfl_sync(FULL, kv, 3), k4 = __shfl_sync(FULL, kv, 4), k5 = __shfl_sync(FULL, kv, 5);
    float k6 = __shfl_sync(FULL, kv, 6), k7 = __shfl_sync(FULL, kv, 7), k8 = __shfl_sync(FULL, kv, 8);
    float bias = b2[c] - m2[c] * sc;

    bool act = lane < 28;
    int col = lane * 4;
    int y0 = s7 * 16;

#define LOAD4(y) ((act && (unsigned)(y) < (unsigned)IMGW) \
                      ? __ldg((const float4*)&in[(y) * IMGW + col]) \
                      : make_float4(0.f, 0.f, 0.f, 0.f))

    float4 rA = LOAD4(y0 - 1);
    float4 rB = LOAD4(y0);
    float4 rC = LOAD4(y0 + 1);
    float Al, Ar, Bl, Br;
    {
        float u = __shfl_up_sync(FULL, rA.w, 1);
        Al = (lane == 0) ? 0.f : u;
        Ar = __shfl_down_sync(FULL, rA.x, 1);
        u = __shfl_up_sync(FULL, rB.w, 1);
        Bl = (lane == 0) ? 0.f : u;
        Br = __shfl_down_sync(FULL, rB.x, 1);
    }

    float tsum = 0.f;
#pragma unroll
    for (int i = 0; i < 16; i++) {
        // prefetch next row BEFORE consuming rC (shuffles) -> MLP 2
        float4 rD = (i < 15) ? LOAD4(y0 + i + 2) : make_float4(0.f, 0.f, 0.f, 0.f);
        float u = __shfl_up_sync(FULL, rC.w, 1);
        float Cl = (lane == 0) ? 0.f : u;
        float Cr = __shfl_down_sync(FULL, rC.x, 1);

        float a0 = bias, a1 = bias, a2 = bias, a3 = bias;
        a0 = fmaf(k0, Al,   fmaf(k1, rA.x, fmaf(k2, rA.y, a0)));
        a1 = fmaf(k0, rA.x, fmaf(k1, rA.y, fmaf(k2, rA.z, a1)));
        a2 = fmaf(k0, rA.y, fmaf(k1, rA.z, fmaf(k2, rA.w, a2)));
        a3 = fmaf(k0, rA.z, fmaf(k1, rA.w, fmaf(k2, Ar,   a3)));
        a0 = fmaf(k3, Bl,   fmaf(k4, rB.x, fmaf(k5, rB.y, a0)));
        a1 = fmaf(k3, rB.x, fmaf(k4, rB.y, fmaf(k5, rB.z, a1)));
        a2 = fmaf(k3, rB.y, fmaf(k4, rB.z, fmaf(k5, rB.w, a2)));
        a3 = fmaf(k3, rB.z, fmaf(k4, rB.w, fmaf(k5, Br,   a3)));
        a0 = fmaf(k6, Cl,   fmaf(k7, rC.x, fmaf(k8, rC.y, a0)));
        a1 = fmaf(k6, rC.x, fmaf(k7, rC.y, fmaf(k8, rC.z, a1)));
        a2 = fmaf(k6, rC.y, fmaf(k7, rC.z, fmaf(k8, rC.w, a2)));
        a3 = fmaf(k6, rC.z, fmaf(k7, rC.w, fmaf(k8, Cr,   a3)));
        float4 r;
        r.x = fmaxf(a0, 0.f); r.y = fmaxf(a1, 0.f);
        r.z = fmaxf(a2, 0.f); r.w = fmaxf(a3, 0.f);
        if (act) {
            *(float4*)&op[(y0 + i) * IMGW + col] = r;
            tsum += r.x + r.y + r.z + r.w;
        }
        rA = rB; Al = Bl; Ar = Br;
        rB = rC; Bl = Cl; Br = Cr;
        rC = rD;
    }
#undef LOAD4

    for (int o = 16; o; o >>= 1) tsum += __shfl_xor_sync(FULL, tsum, o);
    if (lane == 0) atomicAdd(&g_sum2[bc], tsum);
}

// ---- SE MLP -> gates: grid NB x 128, weights staged in smem ----
__global__ __launch_bounds__(128) void se_kernel(
    const float* __restrict__ sw1, const float* __restrict__ sb1,
    const float* __restrict__ sw2, const float* __restrict__ sb2) {
    int b = blockIdx.x;
    int tid = threadIdx.x;
    __shared__ float w1s[32 * 128];
    __shared__ float w2s[128 * 32];
    __shared__ float sm[128];
    __shared__ float h[32];
#pragma unroll
    for (int k = 0; k < 8; k++) {
        ((float4*)w1s)[tid + 128 * k] = ((const float4*)sw1)[tid + 128 * k];
        ((float4*)w2s)[tid + 128 * k] = ((const float4*)sw2)[tid + 128 * k];
    }
    sm[tid] = (tid < 64 ? g_sum1[b * 64 + tid] : g_sum2[b * 64 + tid - 64]) * (1.f / (float)HWSZ);
    __syncthreads();
    {
        int j = tid >> 2, l4 = tid & 3;
        float a = 0.f;
#pragma unroll
        for (int c = 0; c < 32; c++) a += w1s[j * 128 + l4 * 32 + c] * sm[l4 * 32 + c];
        a += __shfl_xor_sync(0xffffffffu, a, 1);
        a += __shfl_xor_sync(0xffffffffu, a, 2);
        if (l4 == 0) h[j] = fmaxf(a + sb1[j], 0.f);
    }
    __syncthreads();
    float a = sb2[tid];
#pragma unroll
    for (int j = 0; j < 32; j++) a += w2s[tid * 32 + j] * h[j];
    g_gates[b * 128 + tid] = sigmoidf_(a);
}

// ---- in-place gate scaling: grid (14, 2048) x 224, one f4/thread ----
__global__ __launch_bounds__(224) void scale_kernel(float* __restrict__ out) {
    int bc = blockIdx.y;
    int fq = blockIdx.x * 224 + threadIdx.x;     // 0..3135
    float g = __ldg(&g_gates[bc]);
    float4* p = ((float4*)out) + (size_t)bc * (HWSZ / 4) + fq;
    float4 v = *p;
    v.x *= g; v.y *= g; v.z *= g; v.w *= g;
    *p = v;
}

// ---------------------------------------------------------------
extern "C" void kernel_launch(void* const* d_in, const int* in_sizes, int n_in,
                              void* d_out, int out_size) {
    const float* x    = (const float*)d_in[0];
    const float* rw1  = (const float*)d_in[1];
    const float* rb1  = (const float*)d_in[2];
    const float* w1   = (const float*)d_in[3];
    const float* bn1g = (const float*)d_in[4];
    const float* bn1b = (const float*)d_in[5];
    const float* bn1m = (const float*)d_in[6];
    const float* bn1v = (const float*)d_in[7];
    const float* rw2  = (const float*)d_in[8];
    const float* rb2  = (const float*)d_in[9];
    const float* w2   = (const float*)d_in[10];
    const float* bn2g = (const float*)d_in[11];
    const float* bn2b = (const float*)d_in[12];
    const float* bn2m = (const float*)d_in[13];
    const float* bn2v = (const float*)d_in[14];
    const float* sw1  = (const float*)d_in[15];
    const float* sb1  = (const float*)d_in[16];
    const float* sw2  = (const float*)d_in[17];
    const float* sb2  = (const float*)d_in[18];
    float* out = (float*)d_out;

    const int conv1_smem_bytes = (2 * 64 * KROW + 2 * 64 * XROW) * 2;  // 86016
    cudaFuncSetAttribute(conv1_mma_kernel, cudaFuncAttributeMaxDynamicSharedMemorySize,
                         conv1_smem_bytes);

    pool1_kernel<<<NB * 64, 256>>>(x);
    build_k1_kernel<<<NB, 256>>>(rw1, rb1, w1, bn1g, bn1v);
    conv1_mma_kernel<<<dim3(HWSZ / 256, NB), 256, conv1_smem_bytes>>>(
        x, bn1g, bn1b, bn1m, bn1v, out);
    dw_kernel<<<1792, 128>>>(
        rw2, rb2, w2, bn2g, bn2b, bn2m, bn2v, out);
    se_kernel<<<NB, 128>>>(sw1, sb1, sw2, sb2);
    scale_kernel<<<dim3(14, NB * 128), 224>>>(out);
}

// round 11
// speedup vs baseline: 1.0459x; 1.0459x over previous
#include <cuda_runtime.h>
#include <cuda_bf16.h>
#include <math.h>

#define HWSZ 12544      // 112*112
#define IMGW 112
#define NB   16
#define EPSV 1e-5f

// ---- scratch (tiny) ----
__device__ float g_pooled[NB * 64];
__device__ float g_k1[NB * 64 * 64];   // [b][o][i], BN1 scale folded
__device__ float g_k2[NB * 64 * 16];   // [bc][0..8]=coeffs, [9]=bias
__device__ float g_sum1[NB * 64];      // post-act x1 channel sums
__device__ float g_sum2[NB * 64];      // post-act x2 channel sums
__device__ float g_gates[NB * 128];

__device__ __forceinline__ float sigmoidf_(float x) { return 1.f / (1.f + expf(-x)); }

__device__ __forceinline__ unsigned smem_u32(const void* p) {
    unsigned r;
    asm("{ .reg .u64 t; cvta.to.shared.u64 t, %1; cvt.u32.u64 %0, t; }" : "=r"(r) : "l"(p));
    return r;
}
// pack two floats -> bf16x2 word: low half = lo, high half = hi
__device__ __forceinline__ unsigned pack_bf16x2(float lo, float hi) {
    unsigned r;
    asm("cvt.rn.bf16x2.f32 %0, %1, %2;" : "=r"(r) : "f"(hi), "f"(lo));
    return r;
}
#define LDSM_X4(r0, r1, r2, r3, addr) \
    asm volatile("ldmatrix.sync.aligned.m8n8.x4.shared.b16 {%0,%1,%2,%3}, [%4];" \
                 : "=r"(r0), "=r"(r1), "=r"(r2), "=r"(r3) : "r"(addr))
#define LDSM_X2_T(r0, r1, addr) \
    asm volatile("ldmatrix.sync.aligned.m8n8.x2.trans.shared.b16 {%0,%1}, [%2];" \
                 : "=r"(r0), "=r"(r1) : "r"(addr))
#define MMA_BF16(c, a, b) \
    asm volatile("mma.sync.aligned.m16n8k16.row.col.f32.bf16.bf16.f32 " \
                 "{%0,%1,%2,%3}, {%4,%5,%6,%7}, {%8,%9}, {%0,%1,%2,%3};" \
                 : "+f"((c)[0]), "+f"((c)[1]), "+f"((c)[2]), "+f"((c)[3]) \
                 : "r"((a)[0]), "r"((a)[1]), "r"((a)[2]), "r"((a)[3]), \
                   "r"((b)[0]), "r"((b)[1]))

// ---- mean over HW per (b,c) + zero sums: grid 1024 x 256 ----
__global__ __launch_bounds__(256) void pool1_kernel(const float* __restrict__ x) {
    int bc = blockIdx.x;
    if (threadIdx.x == 0) { g_sum1[bc] = 0.f; g_sum2[bc] = 0.f; }
    const float4* p = (const float4*)(x + (size_t)bc * HWSZ);
    float s = 0.f;
    for (int i = threadIdx.x; i < HWSZ / 4; i += 256) {
        float4 v = p[i];
        s += v.x + v.y + v.z + v.w;
    }
    for (int o = 16; o; o >>= 1) s += __shfl_xor_sync(0xffffffffu, s, o);
    __shared__ float red[8];
    if ((threadIdx.x & 31) == 0) red[threadIdx.x >> 5] = s;
    __syncthreads();
    if (threadIdx.x < 8) {
        s = red[threadIdx.x];
        for (int o = 4; o; o >>= 1) s += __shfl_xor_sync(0xffu, s, o);
        if (threadIdx.x == 0) g_pooled[bc] = s * (1.f / (float)HWSZ);
    }
}

// ---- r1 + mixed 1x1 kernel (BN1 scale folded), [o][i] layout: grid NB x 256 ----
__global__ __launch_bounds__(256) void build_k1_kernel(
    const float* __restrict__ rw1, const float* __restrict__ rb1,
    const float* __restrict__ w1,
    const float* __restrict__ g1, const float* __restrict__ v1) {
    int b = blockIdx.x;
    __shared__ float r1s[4];
    if (threadIdx.x < 4) {
        int e = threadIdx.x;
        float a = rb1[e];
        for (int i = 0; i < 64; i++) a += g_pooled[b * 64 + i] * rw1[e * 64 + i];
        r1s[e] = sigmoidf_(a);
    }
    __syncthreads();
    for (int idx = threadIdx.x; idx < 4096; idx += 256) {
        int o = idx >> 6;
        float a = 0.f;
#pragma unroll
        for (int e = 0; e < 4; e++) a += r1s[e] * w1[e * 4096 + idx];
        float sc = g1[o] * rsqrtf(v1[o] + EPSV);
        g_k1[b * 4096 + idx] = a * sc;    // layout [o][i]
    }
}

// ---- dynamic 1x1 conv via bf16-split tensor cores (round-8 proven) ----
#define KROW 72     // A row pad (bf16): 144B -> 16B bank phase
#define XROW 264    // B row pad (bf16): 528B -> 16B bank phase
__global__ __launch_bounds__(256, 2) void conv1_mma_kernel(
    const float* __restrict__ x,
    const float* __restrict__ g1, const float* __restrict__ b1,
    const float* __restrict__ m1, const float* __restrict__ v1,
    float* __restrict__ out) {
    extern __shared__ __nv_bfloat16 cs[];
    __nv_bfloat16* kh = cs;                    // [64][KROW]
    __nv_bfloat16* kl = kh + 64 * KROW;
    __nv_bfloat16* xh = kl + 64 * KROW;        // [64][XROW]
    __nv_bfloat16* xl = xh + 64 * XROW;
    const unsigned FULL = 0xffffffffu;

    int b = blockIdx.y;
    int p0 = blockIdx.x * 256;
    int tid = threadIdx.x;

#pragma unroll
    for (int t = 0; t < 16; t++) {
        int idx = tid + 256 * t;               // f4 index
        int row = idx >> 6, col = (idx & 63) << 2;
        float4 v = *(const float4*)&x[((size_t)(b * 64 + row)) * HWSZ + p0 + col];
        float h0 = __bfloat162float(__float2bfloat16(v.x));
        float h1 = __bfloat162float(__float2bfloat16(v.y));
        float h2 = __bfloat162float(__float2bfloat16(v.z));
        float h3 = __bfloat162float(__float2bfloat16(v.w));
        uint2 hw = make_uint2(pack_bf16x2(v.x, v.y), pack_bf16x2(v.z, v.w));
        uint2 lw = make_uint2(pack_bf16x2(v.x - h0, v.y - h1),
                              pack_bf16x2(v.z - h2, v.w - h3));
        *(uint2*)&xh[row * XROW + col] = hw;
        *(uint2*)&xl[row * XROW + col] = lw;
    }
#pragma unroll
    for (int t = 0; t < 8; t++) {
        int pidx = tid + 256 * t;              // pair index 0..2047
        int o = pidx >> 5, i2 = (pidx & 31) << 1;
        float a0 = g_k1[b * 4096 + o * 64 + i2];
        float a1 = g_k1[b * 4096 + o * 64 + i2 + 1];
        float h0 = __bfloat162float(__float2bfloat16(a0));
        float h1 = __bfloat162float(__float2bfloat16(a1));
        *(unsigned*)&kh[o * KROW + i2] = pack_bf16x2(a0, a1);
        *(unsigned*)&kl[o * KROW + i2] = pack_bf16x2(a0 - h0, a1 - h1);
    }
    __syncthreads();

    int warp = tid >> 5, lane = tid & 31;
    int mw = warp & 3, nw = warp >> 2;

    float C[16][4];
#pragma unroll
    for (int j = 0; j < 16; j++)
#pragma unroll
        for (int q = 0; q < 4; q++) C[j][q] = 0.f;

    int arow = mw * 16 + (lane & 15);
    int acol = (lane & 16) ? 8 : 0;
    unsigned a_h = smem_u32(kh) + (arow * KROW + acol) * 2;
    unsigned a_l = smem_u32(kl) + (arow * KROW + acol) * 2;
    unsigned b_h0 = smem_u32(xh) + ((lane & 15) * XROW + nw * 128) * 2;
    unsigned b_l0 = smem_u32(xl) + ((lane & 15) * XROW + nw * 128) * 2;

#pragma unroll
    for (int kt = 0; kt < 4; kt++) {
        unsigned Ah[4], Al[4];
        LDSM_X4(Ah[0], Ah[1], Ah[2], Ah[3], a_h + kt * 16 * 2);
        LDSM_X4(Al[0], Al[1], Al[2], Al[3], a_l + kt * 16 * 2);
        unsigned bh = b_h0 + kt * 16 * XROW * 2;
        unsigned bl = b_l0 + kt * 16 * XROW * 2;
#pragma unroll
        for (int j = 0; j < 16; j++) {
            unsigned Bh[2], Bl[2];
            LDSM_X2_T(Bh[0], Bh[1], bh + j * 16);
            LDSM_X2_T(Bl[0], Bl[1], bl + j * 16);
            MMA_BF16(C[j], Ah, Bh);
            MMA_BF16(C[j], Ah, Bl);
            MMA_BF16(C[j], Al, Bh);
        }
    }

    int r0 = mw * 16 + (lane >> 2);
    int r1 = r0 + 8;
    float sc0 = g1[r0] * rsqrtf(v1[r0] + EPSV);
    float sh0 = b1[r0] - m1[r0] * sc0;
    float sc1 = g1[r1] * rsqrtf(v1[r1] + EPSV);
    float sh1 = b1[r1] - m1[r1] * sc1;
    float* op0 = out + ((size_t)(b * 128 + r0)) * HWSZ + p0 + nw * 128 + (lane & 3) * 2;
    float* op1 = out + ((size_t)(b * 128 + r1)) * HWSZ + p0 + nw * 128 + (lane & 3) * 2;
    float s0 = 0.f, s1 = 0.f;
#pragma unroll
    for (int j = 0; j < 16; j++) {
        float c0 = fmaxf(C[j][0] + sh0, 0.f), c1 = fmaxf(C[j][1] + sh0, 0.f);
        float c2 = fmaxf(C[j][2] + sh1, 0.f), c3 = fmaxf(C[j][3] + sh1, 0.f);
        *(float2*)&op0[j * 8] = make_float2(c0, c1);
        *(float2*)&op1[j * 8] = make_float2(c2, c3);
        s0 += c0 + c1; s1 += c2 + c3;
    }
    s0 += __shfl_xor_sync(FULL, s0, 1); s0 += __shfl_xor_sync(FULL, s0, 2);
    s1 += __shfl_xor_sync(FULL, s1, 1); s1 += __shfl_xor_sync(FULL, s1, 2);
    if ((lane & 3) == 0) {
        atomicAdd(&g_sum1[b * 64 + r0], s0);
        atomicAdd(&g_sum1[b * 64 + r1], s1);
    }
}

// ---- r2 routing + 3x3 coeff mix + BN2 fold, once per (b,c): grid NB x 64 ----
__global__ __launch_bounds__(64) void build_k2_kernel(
    const float* __restrict__ rw2, const float* __restrict__ rb2,
    const float* __restrict__ w2,
    const float* __restrict__ g2, const float* __restrict__ b2,
    const float* __restrict__ m2, const float* __restrict__ v2) {
    int b = blockIdx.x;
    int c = threadIdx.x;
    __shared__ float r2s[4];
    if (c < 4) {
        float a = rb2[c];
        const float* rw = rw2 + c * 64;
        const float* su = g_sum1 + b * 64;
        for (int cc = 0; cc < 64; cc++) a += su[cc] * (1.f / (float)HWSZ) * rw[cc];
        r2s[c] = sigmoidf_(a);
    }
    __syncthreads();
    float sc = g2[c] * rsqrtf(v2[c] + EPSV);
    float* kp = g_k2 + (b * 64 + c) * 16;
#pragma unroll
    for (int t = 0; t < 9; t++) {
        const float* wp = w2 + c * 9 + t;
        float a = r2s[0] * wp[0] + r2s[1] * wp[576] + r2s[2] * wp[1152] + r2s[3] * wp[1728];
        kp[t] = a * sc;
    }
    kp[9] = b2[c] - m2[c] * sc;
}

// ---- dynamic 3x3 depthwise: pipelined register-rolling stencil ----
// one warp = one (channel, 16-row strip); block 128 (4 warps), grid 1792
__global__ __launch_bounds__(128) void dw_kernel(float* __restrict__ out) {
    const unsigned FULL = 0xffffffffu;
    int lane = threadIdx.x & 31;
    int gw = blockIdx.x * 4 + (threadIdx.x >> 5);   // 0..7167
    int bc = gw / 7, s7 = gw % 7;
    int b = bc >> 6, c = bc & 63;
    const float* in = out + ((size_t)(b * 128 + c)) * HWSZ;       // x1 channel
    float* op = out + ((size_t)(b * 128 + 64 + c)) * HWSZ;        // x2 channel

    // precomputed coeffs: 10 coalesced loads + broadcast shuffles
    float kv = (lane < 10) ? __ldg(&g_k2[bc * 16 + lane]) : 0.f;
    float k0 = __shfl_sync(FULL, kv, 0), k1 = __shfl_sync(FULL, kv, 1), k2 = __shfl_sync(FULL, kv, 2);
    float k3 = __shfl_sync(FULL, kv, 3), k4 = __shfl_sync(FULL, kv, 4), k5 = __shfl_sync(FULL, kv, 5);
    float k6 = __shfl_sync(FULL, kv, 6), k7 = __shfl_sync(FULL, kv, 7), k8 = __shfl_sync(FULL, kv, 8);
    float bias = __shfl_sync(FULL, kv, 9);

    bool act = lane < 28;
    int col = lane * 4;
    int y0 = s7 * 16;

#define LOAD4(y) ((act && (unsigned)(y) < (unsigned)IMGW) \
                      ? __ldg((const float4*)&in[(y) * IMGW + col]) \
                      : make_float4(0.f, 0.f, 0.f, 0.f))

    float4 rA = LOAD4(y0 - 1);
    float4 rB = LOAD4(y0);
    float4 rC = LOAD4(y0 + 1);
    float Al, Ar, Bl, Br;
    {
        float u = __shfl_up_sync(FULL, rA.w, 1);
        Al = (lane == 0) ? 0.f : u;
        Ar = __shfl_down_sync(FULL, rA.x, 1);
        u = __shfl_up_sync(FULL, rB.w, 1);
        Bl = (lane == 0) ? 0.f : u;
        Br = __shfl_down_sync(FULL, rB.x, 1);
    }

    float tsum = 0.f;
#pragma unroll
    for (int i = 0; i < 16; i++) {
        // prefetch next row BEFORE consuming rC (shuffles) -> MLP 2
        float4 rD = (i < 15) ? LOAD4(y0 + i + 2) : make_float4(0.f, 0.f, 0.f, 0.f);
        float u = __shfl_up_sync(FULL, rC.w, 1);
        float Cl = (lane == 0) ? 0.f : u;
        float Cr = __shfl_down_sync(FULL, rC.x, 1);

        float a0 = bias, a1 = bias, a2 = bias, a3 = bias;
        a0 = fmaf(k0, Al,   fmaf(k1, rA.x, fmaf(k2, rA.y, a0)));
        a1 = fmaf(k0, rA.x, fmaf(k1, rA.y, fmaf(k2, rA.z, a1)));
        a2 = fmaf(k0, rA.y, fmaf(k1, rA.z, fmaf(k2, rA.w, a2)));
        a3 = fmaf(k0, rA.z, fmaf(k1, rA.w, fmaf(k2, Ar,   a3)));
        a0 = fmaf(k3, Bl,   fmaf(k4, rB.x, fmaf(k5, rB.y, a0)));
        a1 = fmaf(k3, rB.x, fmaf(k4, rB.y, fmaf(k5, rB.z, a1)));
        a2 = fmaf(k3, rB.y, fmaf(k4, rB.z, fmaf(k5, rB.w, a2)));
        a3 = fmaf(k3, rB.z, fmaf(k4, rB.w, fmaf(k5, Br,   a3)));
        a0 = fmaf(k6, Cl,   fmaf(k7, rC.x, fmaf(k8, rC.y, a0)));
        a1 = fmaf(k6, rC.x, fmaf(k7, rC.y, fmaf(k8, rC.z, a1)));
        a2 = fmaf(k6, rC.y, fmaf(k7, rC.z, fmaf(k8, rC.w, a2)));
        a3 = fmaf(k6, rC.z, fmaf(k7, rC.w, fmaf(k8, Cr,   a3)));
        float4 r;
        r.x = fmaxf(a0, 0.f); r.y = fmaxf(a1, 0.f);
        r.z = fmaxf(a2, 0.f); r.w = fmaxf(a3, 0.f);
        if (act) {
            *(float4*)&op[(y0 + i) * IMGW + col] = r;
            tsum += r.x + r.y + r.z + r.w;
        }
        rA = rB; Al = Bl; Ar = Br;
        rB = rC; Bl = Cl; Br = Cr;
        rC = rD;
    }
#undef LOAD4

    for (int o = 16; o; o >>= 1) tsum += __shfl_xor_sync(FULL, tsum, o);
    if (lane == 0) atomicAdd(&g_sum2[bc], tsum);
}

// ---- SE MLP -> gates: grid NB x 128, weights staged in smem ----
__global__ __launch_bounds__(128) void se_kernel(
    const float* __restrict__ sw1, const float* __restrict__ sb1,
    const float* __restrict__ sw2, const float* __restrict__ sb2) {
    int b = blockIdx.x;
    int tid = threadIdx.x;
    __shared__ float w1s[32 * 128];
    __shared__ float w2s[128 * 32];
    __shared__ float sm[128];
    __shared__ float h[32];
#pragma unroll
    for (int k = 0; k < 8; k++) {
        ((float4*)w1s)[tid + 128 * k] = ((const float4*)sw1)[tid + 128 * k];
        ((float4*)w2s)[tid + 128 * k] = ((const float4*)sw2)[tid + 128 * k];
    }
    sm[tid] = (tid < 64 ? g_sum1[b * 64 + tid] : g_sum2[b * 64 + tid - 64]) * (1.f / (float)HWSZ);
    __syncthreads();
    {
        int j = tid >> 2, l4 = tid & 3;
        float a = 0.f;
#pragma unroll
        for (int c = 0; c < 32; c++) a += w1s[j * 128 + l4 * 32 + c] * sm[l4 * 32 + c];
        a += __shfl_xor_sync(0xffffffffu, a, 1);
        a += __shfl_xor_sync(0xffffffffu, a, 2);
        if (l4 == 0) h[j] = fmaxf(a + sb1[j], 0.f);
    }
    __syncthreads();
    float a = sb2[tid];
#pragma unroll
    for (int j = 0; j < 32; j++) a += w2s[tid * 32 + j] * h[j];
    g_gates[b * 128 + tid] = sigmoidf_(a);
}

// ---- in-place gate scaling: grid (14, 2048) x 224, one f4/thread ----
__global__ __launch_bounds__(224) void scale_kernel(float* __restrict__ out) {
    int bc = blockIdx.y;
    int fq = blockIdx.x * 224 + threadIdx.x;     // 0..3135
    float g = __ldg(&g_gates[bc]);
    float4* p = ((float4*)out) + (size_t)bc * (HWSZ / 4) + fq;
    float4 v = *p;
    v.x *= g; v.y *= g; v.z *= g; v.w *= g;
    *p = v;
}

// ---------------------------------------------------------------
extern "C" void kernel_launch(void* const* d_in, const int* in_sizes, int n_in,
                              void* d_out, int out_size) {
    const float* x    = (const float*)d_in[0];
    const float* rw1  = (const float*)d_in[1];
    const float* rb1  = (const float*)d_in[2];
    const float* w1   = (const float*)d_in[3];
    const float* bn1g = (const float*)d_in[4];
    const float* bn1b = (const float*)d_in[5];
    const float* bn1m = (const float*)d_in[6];
    const float* bn1v = (const float*)d_in[7];
    const float* rw2  = (const float*)d_in[8];
    const float* rb2  = (const float*)d_in[9];
    const float* w2   = (const float*)d_in[10];
    const float* bn2g = (const float*)d_in[11];
    const float* bn2b = (const float*)d_in[12];
    const float* bn2m = (const float*)d_in[13];
    const float* bn2v = (const float*)d_in[14];
    const float* sw1  = (const float*)d_in[15];
    const float* sb1  = (const float*)d_in[16];
    const float* sw2  = (const float*)d_in[17];
    const float* sb2  = (const float*)d_in[18];
    float* out = (float*)d_out;

    const int conv1_smem_bytes = (2 * 64 * KROW + 2 * 64 * XROW) * 2;  // 86016
    cudaFuncSetAttribute(conv1_mma_kernel, cudaFuncAttributeMaxDynamicSharedMemorySize,
                         conv1_smem_bytes);

    pool1_kernel<<<NB * 64, 256>>>(x);
    build_k1_kernel<<<NB, 256>>>(rw1, rb1, w1, bn1g, bn1v);
    conv1_mma_kernel<<<dim3(HWSZ / 256, NB), 256, conv1_smem_bytes>>>(
        x, bn1g, bn1b, bn1m, bn1v, out);
    build_k2_kernel<<<NB, 64>>>(rw2, rb2, w2, bn2g, bn2b, bn2m, bn2v);
    dw_kernel<<<1792, 128>>>(out);
    se_kernel<<<NB, 128>>>(sw1, sb1, sw2, sb2);
    scale_kernel<<<dim3(14, NB * 128), 224>>>(out);
}

// round 12
// speedup vs baseline: 1.0569x; 1.0105x over previous
#include <cuda_runtime.h>
#include <cuda_bf16.h>
#include <math.h>

#define HWSZ 12544      // 112*112
#define IMGW 112
#define NB   16
#define EPSV 1e-5f

// ---- scratch (tiny) ----
__device__ float g_pooled[NB * 64];
__device__ float g_k1[NB * 64 * 64];   // [b][o][i], BN1 scale folded
__device__ float g_k2[NB * 64 * 16];   // [bc][0..8]=coeffs, [9]=bias
__device__ float g_sum1[NB * 64];      // post-act x1 channel sums
__device__ float g_sum2[NB * 64];      // post-act x2 channel sums
__device__ float g_gates[NB * 128];

__device__ __forceinline__ float sigmoidf_(float x) { return 1.f / (1.f + expf(-x)); }

__device__ __forceinline__ unsigned smem_u32(const void* p) {
    unsigned r;
    asm("{ .reg .u64 t; cvta.to.shared.u64 t, %1; cvt.u32.u64 %0, t; }" : "=r"(r) : "l"(p));
    return r;
}
// pack two floats -> bf16x2 word: low half = lo, high half = hi
__device__ __forceinline__ unsigned pack_bf16x2(float lo, float hi) {
    unsigned r;
    asm("cvt.rn.bf16x2.f32 %0, %1, %2;" : "=r"(r) : "f"(hi), "f"(lo));
    return r;
}
#define LDSM_X4(r0, r1, r2, r3, addr) \
    asm volatile("ldmatrix.sync.aligned.m8n8.x4.shared.b16 {%0,%1,%2,%3}, [%4];" \
                 : "=r"(r0), "=r"(r1), "=r"(r2), "=r"(r3) : "r"(addr))
#define LDSM_X2_T(r0, r1, addr) \
    asm volatile("ldmatrix.sync.aligned.m8n8.x2.trans.shared.b16 {%0,%1}, [%2];" \
                 : "=r"(r0), "=r"(r1) : "r"(addr))
#define MMA_BF16(c, a, b) \
    asm volatile("mma.sync.aligned.m16n8k16.row.col.f32.bf16.bf16.f32 " \
                 "{%0,%1,%2,%3}, {%4,%5,%6,%7}, {%8,%9}, {%0,%1,%2,%3};" \
                 : "+f"((c)[0]), "+f"((c)[1]), "+f"((c)[2]), "+f"((c)[3]) \
                 : "r"((a)[0]), "r"((a)[1]), "r"((a)[2]), "r"((a)[3]), \
                   "r"((b)[0]), "r"((b)[1]))

// ---- mean over HW per (b,c) + zero sums: grid 1024 x 256 ----
__global__ __launch_bounds__(256) void pool1_kernel(const float* __restrict__ x) {
    int bc = blockIdx.x;
    if (threadIdx.x == 0) { g_sum1[bc] = 0.f; g_sum2[bc] = 0.f; }
    const float4* p = (const float4*)(x + (size_t)bc * HWSZ);
    float s = 0.f;
    for (int i = threadIdx.x; i < HWSZ / 4; i += 256) {
        float4 v = p[i];
        s += v.x + v.y + v.z + v.w;
    }
    for (int o = 16; o; o >>= 1) s += __shfl_xor_sync(0xffffffffu, s, o);
    __shared__ float red[8];
    if ((threadIdx.x & 31) == 0) red[threadIdx.x >> 5] = s;
    __syncthreads();
    if (threadIdx.x < 8) {
        s = red[threadIdx.x];
        for (int o = 4; o; o >>= 1) s += __shfl_xor_sync(0xffu, s, o);
        if (threadIdx.x == 0) g_pooled[bc] = s * (1.f / (float)HWSZ);
    }
}

// ---- r1 + mixed 1x1 kernel (BN1 scale folded), [o][i] layout: grid NB x 256 ----
__global__ __launch_bounds__(256) void build_k1_kernel(
    const float* __restrict__ rw1, const float* __restrict__ rb1,
    const float* __restrict__ w1,
    const float* __restrict__ g1, const float* __restrict__ v1) {
    int b = blockIdx.x;
    __shared__ float r1s[4];
    if (threadIdx.x < 128) {
        int e = threadIdx.x >> 5, lane = threadIdx.x & 31;
        const float* rw = rw1 + e * 64;
        const float* pl = g_pooled + b * 64;
        float a = pl[lane] * rw[lane] + pl[lane + 32] * rw[lane + 32];
        for (int o = 16; o; o >>= 1) a += __shfl_xor_sync(0xffffffffu, a, o);
        if (lane == 0) r1s[e] = sigmoidf_(a + rb1[e]);
    }
    __syncthreads();
    for (int idx = threadIdx.x; idx < 4096; idx += 256) {
        int o = idx >> 6;
        float a = 0.f;
#pragma unroll
        for (int e = 0; e < 4; e++) a += r1s[e] * w1[e * 4096 + idx];
        float sc = g1[o] * rsqrtf(v1[o] + EPSV);
        g_k1[b * 4096 + idx] = a * sc;    // layout [o][i]
    }
}

// ---- dynamic 1x1 conv via bf16-split tensor cores (round-8 proven) ----
#define KROW 72     // A row pad (bf16): 144B -> 16B bank phase
#define XROW 264    // B row pad (bf16): 528B -> 16B bank phase
__global__ __launch_bounds__(256, 2) void conv1_mma_kernel(
    const float* __restrict__ x,
    const float* __restrict__ g1, const float* __restrict__ b1,
    const float* __restrict__ m1, const float* __restrict__ v1,
    float* __restrict__ out) {
    extern __shared__ __nv_bfloat16 cs[];
    __nv_bfloat16* kh = cs;                    // [64][KROW]
    __nv_bfloat16* kl = kh + 64 * KROW;
    __nv_bfloat16* xh = kl + 64 * KROW;        // [64][XROW]
    __nv_bfloat16* xl = xh + 64 * XROW;
    const unsigned FULL = 0xffffffffu;

    int b = blockIdx.y;
    int p0 = blockIdx.x * 256;
    int tid = threadIdx.x;

#pragma unroll
    for (int t = 0; t < 16; t++) {
        int idx = tid + 256 * t;               // f4 index
        int row = idx >> 6, col = (idx & 63) << 2;
        float4 v = *(const float4*)&x[((size_t)(b * 64 + row)) * HWSZ + p0 + col];
        float h0 = __bfloat162float(__float2bfloat16(v.x));
        float h1 = __bfloat162float(__float2bfloat16(v.y));
        float h2 = __bfloat162float(__float2bfloat16(v.z));
        float h3 = __bfloat162float(__float2bfloat16(v.w));
        uint2 hw = make_uint2(pack_bf16x2(v.x, v.y), pack_bf16x2(v.z, v.w));
        uint2 lw = make_uint2(pack_bf16x2(v.x - h0, v.y - h1),
                              pack_bf16x2(v.z - h2, v.w - h3));
        *(uint2*)&xh[row * XROW + col] = hw;
        *(uint2*)&xl[row * XROW + col] = lw;
    }
#pragma unroll
    for (int t = 0; t < 8; t++) {
        int pidx = tid + 256 * t;              // pair index 0..2047
        int o = pidx >> 5, i2 = (pidx & 31) << 1;
        float a0 = g_k1[b * 4096 + o * 64 + i2];
        float a1 = g_k1[b * 4096 + o * 64 + i2 + 1];
        float h0 = __bfloat162float(__float2bfloat16(a0));
        float h1 = __bfloat162float(__float2bfloat16(a1));
        *(unsigned*)&kh[o * KROW + i2] = pack_bf16x2(a0, a1);
        *(unsigned*)&kl[o * KROW + i2] = pack_bf16x2(a0 - h0, a1 - h1);
    }
    __syncthreads();

    int warp = tid >> 5, lane = tid & 31;
    int mw = warp & 3, nw = warp >> 2;

    float C[16][4];
#pragma unroll
    for (int j = 0; j < 16; j++)
#pragma unroll
        for (int q = 0; q < 4; q++) C[j][q] = 0.f;

    int arow = mw * 16 + (lane & 15);
    int acol = (lane & 16) ? 8 : 0;
    unsigned a_h = smem_u32(kh) + (arow * KROW + acol) * 2;
    unsigned a_l = smem_u32(kl) + (arow * KROW + acol) * 2;
    unsigned b_h0 = smem_u32(xh) + ((lane & 15) * XROW + nw * 128) * 2;
    unsigned b_l0 = smem_u32(xl) + ((lane & 15) * XROW + nw * 128) * 2;

#pragma unroll
    for (int kt = 0; kt < 4; kt++) {
        unsigned Ah[4], Al[4];
        LDSM_X4(Ah[0], Ah[1], Ah[2], Ah[3], a_h + kt * 16 * 2);
        LDSM_X4(Al[0], Al[1], Al[2], Al[3], a_l + kt * 16 * 2);
        unsigned bh = b_h0 + kt * 16 * XROW * 2;
        unsigned bl = b_l0 + kt * 16 * XROW * 2;
#pragma unroll
        for (int j = 0; j < 16; j++) {
            unsigned Bh[2], Bl[2];
            LDSM_X2_T(Bh[0], Bh[1], bh + j * 16);
            LDSM_X2_T(Bl[0], Bl[1], bl + j * 16);
            MMA_BF16(C[j], Ah, Bh);
            MMA_BF16(C[j], Ah, Bl);
            MMA_BF16(C[j], Al, Bh);
        }
    }

    int r0 = mw * 16 + (lane >> 2);
    int r1 = r0 + 8;
    float sc0 = g1[r0] * rsqrtf(v1[r0] + EPSV);
    float sh0 = b1[r0] - m1[r0] * sc0;
    float sc1 = g1[r1] * rsqrtf(v1[r1] + EPSV);
    float sh1 = b1[r1] - m1[r1] * sc1;
    float* op0 = out + ((size_t)(b * 128 + r0)) * HWSZ + p0 + nw * 128 + (lane & 3) * 2;
    float* op1 = out + ((size_t)(b * 128 + r1)) * HWSZ + p0 + nw * 128 + (lane & 3) * 2;
    float s0 = 0.f, s1 = 0.f;
#pragma unroll
    for (int j = 0; j < 16; j++) {
        float c0 = fmaxf(C[j][0] + sh0, 0.f), c1 = fmaxf(C[j][1] + sh0, 0.f);
        float c2 = fmaxf(C[j][2] + sh1, 0.f), c3 = fmaxf(C[j][3] + sh1, 0.f);
        *(float2*)&op0[j * 8] = make_float2(c0, c1);
        *(float2*)&op1[j * 8] = make_float2(c2, c3);
        s0 += c0 + c1; s1 += c2 + c3;
    }
    s0 += __shfl_xor_sync(FULL, s0, 1); s0 += __shfl_xor_sync(FULL, s0, 2);
    s1 += __shfl_xor_sync(FULL, s1, 1); s1 += __shfl_xor_sync(FULL, s1, 2);
    if ((lane & 3) == 0) {
        atomicAdd(&g_sum1[b * 64 + r0], s0);
        atomicAdd(&g_sum1[b * 64 + r1], s1);
    }
}

// ---- r2 routing + 3x3 coeff mix + BN2 fold: grid NB x 128 ----
// warp e computes expert-e dot in parallel (2 elems/lane + shuffle reduce)
__global__ __launch_bounds__(128) void build_k2_kernel(
    const float* __restrict__ rw2, const float* __restrict__ rb2,
    const float* __restrict__ w2,
    const float* __restrict__ g2, const float* __restrict__ b2,
    const float* __restrict__ m2, const float* __restrict__ v2) {
    const unsigned FULL = 0xffffffffu;
    int b = blockIdx.x;
    int tid = threadIdx.x;
    int e = tid >> 5, lane = tid & 31;
    __shared__ float r2s[4];
    {
        const float* rw = rw2 + e * 64;
        const float* su = g_sum1 + b * 64;
        float a = su[lane] * rw[lane] + su[lane + 32] * rw[lane + 32];
        for (int o = 16; o; o >>= 1) a += __shfl_xor_sync(FULL, a, o);
        if (lane == 0) r2s[e] = sigmoidf_(a * (1.f / (float)HWSZ) + rb2[e]);
    }
    __syncthreads();
    if (tid < 64) {
        int c = tid;
        float sc = g2[c] * rsqrtf(v2[c] + EPSV);
        float* kp = g_k2 + (b * 64 + c) * 16;
        float e0 = r2s[0], e1 = r2s[1], e2 = r2s[2], e3 = r2s[3];
#pragma unroll
        for (int t = 0; t < 9; t++) {
            const float* wp = w2 + c * 9 + t;
            float a = e0 * wp[0] + e1 * wp[576] + e2 * wp[1152] + e3 * wp[1728];
            kp[t] = a * sc;
        }
        kp[9] = b2[c] - m2[c] * sc;
    }
}

// ---- dynamic 3x3 depthwise: pipelined register-rolling stencil ----
// one warp = one (channel, 16-row strip); block 128 (4 warps), grid 1792
__global__ __launch_bounds__(128) void dw_kernel(float* __restrict__ out) {
    const unsigned FULL = 0xffffffffu;
    int lane = threadIdx.x & 31;
    int gw = blockIdx.x * 4 + (threadIdx.x >> 5);   // 0..7167
    int bc = gw / 7, s7 = gw % 7;
    int b = bc >> 6, c = bc & 63;
    const float* in = out + ((size_t)(b * 128 + c)) * HWSZ;       // x1 channel
    float* op = out + ((size_t)(b * 128 + 64 + c)) * HWSZ;        // x2 channel

    // precomputed coeffs: 10 coalesced loads + broadcast shuffles
    float kv = (lane < 10) ? __ldg(&g_k2[bc * 16 + lane]) : 0.f;
    float k0 = __shfl_sync(FULL, kv, 0), k1 = __shfl_sync(FULL, kv, 1), k2 = __shfl_sync(FULL, kv, 2);
    float k3 = __shfl_sync(FULL, kv, 3), k4 = __shfl_sync(FULL, kv, 4), k5 = __shfl_sync(FULL, kv, 5);
    float k6 = __shfl_sync(FULL, kv, 6), k7 = __shfl_sync(FULL, kv, 7), k8 = __shfl_sync(FULL, kv, 8);
    float bias = __shfl_sync(FULL, kv, 9);

    bool act = lane < 28;
    int col = lane * 4;
    int y0 = s7 * 16;

#define LOAD4(y) ((act && (unsigned)(y) < (unsigned)IMGW) \
                      ? __ldg((const float4*)&in[(y) * IMGW + col]) \
                      : make_float4(0.f, 0.f, 0.f, 0.f))

    float4 rA = LOAD4(y0 - 1);
    float4 rB = LOAD4(y0);
    float4 rC = LOAD4(y0 + 1);
    float Al, Ar, Bl, Br;
    {
        float u = __shfl_up_sync(FULL, rA.w, 1);
        Al = (lane == 0) ? 0.f : u;
        Ar = __shfl_down_sync(FULL, rA.x, 1);
        u = __shfl_up_sync(FULL, rB.w, 1);
        Bl = (lane == 0) ? 0.f : u;
        Br = __shfl_down_sync(FULL, rB.x, 1);
    }

    float tsum = 0.f;
#pragma unroll
    for (int i = 0; i < 16; i++) {
        // prefetch next row BEFORE consuming rC (shuffles) -> MLP 2
        float4 rD = (i < 15) ? LOAD4(y0 + i + 2) : make_float4(0.f, 0.f, 0.f, 0.f);
        float u = __shfl_up_sync(FULL, rC.w, 1);
        float Cl = (lane == 0) ? 0.f : u;
        float Cr = __shfl_down_sync(FULL, rC.x, 1);

        float a0 = bias, a1 = bias, a2 = bias, a3 = bias;
        a0 = fmaf(k0, Al,   fmaf(k1, rA.x, fmaf(k2, rA.y, a0)));
        a1 = fmaf(k0, rA.x, fmaf(k1, rA.y, fmaf(k2, rA.z, a1)));
        a2 = fmaf(k0, rA.y, fmaf(k1, rA.z, fmaf(k2, rA.w, a2)));
        a3 = fmaf(k0, rA.z, fmaf(k1, rA.w, fmaf(k2, Ar,   a3)));
        a0 = fmaf(k3, Bl,   fmaf(k4, rB.x, fmaf(k5, rB.y, a0)));
        a1 = fmaf(k3, rB.x, fmaf(k4, rB.y, fmaf(k5, rB.z, a1)));
        a2 = fmaf(k3, rB.y, fmaf(k4, rB.z, fmaf(k5, rB.w, a2)));
        a3 = fmaf(k3, rB.z, fmaf(k4, rB.w, fmaf(k5, Br,   a3)));
        a0 = fmaf(k6, Cl,   fmaf(k7, rC.x, fmaf(k8, rC.y, a0)));
        a1 = fmaf(k6, rC.x, fmaf(k7, rC.y, fmaf(k8, rC.z, a1)));
        a2 = fmaf(k6, rC.y, fmaf(k7, rC.z, fmaf(k8, rC.w, a2)));
        a3 = fmaf(k6, rC.z, fmaf(k7, rC.w, fmaf(k8, Cr,   a3)));
        float4 r;
        r.x = fmaxf(a0, 0.f); r.y = fmaxf(a1, 0.f);
        r.z = fmaxf(a2, 0.f); r.w = fmaxf(a3, 0.f);
        if (act) {
            *(float4*)&op[(y0 + i) * IMGW + col] = r;
            tsum += r.x + r.y + r.z + r.w;
        }
        rA = rB; Al = Bl; Ar = Br;
        rB = rC; Bl = Cl; Br = Cr;
        rC = rD;
    }
#undef LOAD4

    for (int o = 16; o; o >>= 1) tsum += __shfl_xor_sync(FULL, tsum, o);
    if (lane == 0) atomicAdd(&g_sum2[bc], tsum);
}

// ---- SE MLP -> gates: grid NB x 128, weights staged in smem ----
__global__ __launch_bounds__(128) void se_kernel(
    const float* __restrict__ sw1, const float* __restrict__ sb1,
    const float* __restrict__ sw2, const float* __restrict__ sb2) {
    int b = blockIdx.x;
    int tid = threadIdx.x;
    __shared__ float w1s[32 * 128];
    __shared__ float w2s[128 * 32];
    __shared__ float sm[128];
    __shared__ float h[32];
#pragma unroll
    for (int k = 0; k < 8; k++) {
        ((float4*)w1s)[tid + 128 * k] = ((const float4*)sw1)[tid + 128 * k];
        ((float4*)w2s)[tid + 128 * k] = ((const float4*)sw2)[tid + 128 * k];
    }
    sm[tid] = (tid < 64 ? g_sum1[b * 64 + tid] : g_sum2[b * 64 + tid - 64]) * (1.f / (float)HWSZ);
    __syncthreads();
    {
        int j = tid >> 2, l4 = tid & 3;
        float a = 0.f;
#pragma unroll
        for (int c = 0; c < 32; c++) a += w1s[j * 128 + l4 * 32 + c] * sm[l4 * 32 + c];
        a += __shfl_xor_sync(0xffffffffu, a, 1);
        a += __shfl_xor_sync(0xffffffffu, a, 2);
        if (l4 == 0) h[j] = fmaxf(a + sb1[j], 0.f);
    }
    __syncthreads();
    float a = sb2[tid];
#pragma unroll
    for (int j = 0; j < 32; j++) a += w2s[tid * 32 + j] * h[j];
    g_gates[b * 128 + tid] = sigmoidf_(a);
}

// ---- in-place gate scaling: grid (14, 2048) x 224, one f4/thread ----
__global__ __launch_bounds__(224) void scale_kernel(float* __restrict__ out) {
    int bc = blockIdx.y;
    int fq = blockIdx.x * 224 + threadIdx.x;     // 0..3135
    float g = __ldg(&g_gates[bc]);
    float4* p = ((float4*)out) + (size_t)bc * (HWSZ / 4) + fq;
    float4 v = *p;
    v.x *= g; v.y *= g; v.z *= g; v.w *= g;
    *p = v;
}

// ---------------------------------------------------------------
extern "C" void kernel_launch(void* const* d_in, const int* in_sizes, int n_in,
                              void* d_out, int out_size) {
    const float* x    = (const float*)d_in[0];
    const float* rw1  = (const float*)d_in[1];
    const float* rb1  = (const float*)d_in[2];
    const float* w1   = (const float*)d_in[3];
    const float* bn1g = (const float*)d_in[4];
    const float* bn1b = (const float*)d_in[5];
    const float* bn1m = (const float*)d_in[6];
    const float* bn1v = (const float*)d_in[7];
    const float* rw2  = (const float*)d_in[8];
    const float* rb2  = (const float*)d_in[9];
    const float* w2   = (const float*)d_in[10];
    const float* bn2g = (const float*)d_in[11];
    const float* bn2b = (const float*)d_in[12];
    const float* bn2m = (const float*)d_in[13];
    const float* bn2v = (const float*)d_in[14];
    const float* sw1  = (const float*)d_in[15];
    const float* sb1  = (const float*)d_in[16];
    const float* sw2  = (const float*)d_in[17];
    const float* sb2  = (const float*)d_in[18];
    float* out = (float*)d_out;

    const int conv1_smem_bytes = (2 * 64 * KROW + 2 * 64 * XROW) * 2;  // 86016
    cudaFuncSetAttribute(conv1_mma_kernel, cudaFuncAttributeMaxDynamicSharedMemorySize,
                         conv1_smem_bytes);

    pool1_kernel<<<NB * 64, 256>>>(x);
    build_k1_kernel<<<NB, 256>>>(rw1, rb1, w1, bn1g, bn1v);
    conv1_mma_kernel<<<dim3(HWSZ / 256, NB), 256, conv1_smem_bytes>>>(
        x, bn1g, bn1b, bn1m, bn1v, out);
    build_k2_kernel<<<NB, 128>>>(rw2, rb2, w2, bn2g, bn2b, bn2m, bn2v);
    dw_kernel<<<1792, 128>>>(out);
    se_kernel<<<NB, 128>>>(sw1, sb1, sw2, sb2);
    scale_kernel<<<dim3(14, NB * 128), 224>>>(out);
}